// round 14
// baseline (speedup 1.0000x reference)
#include <cuda_runtime.h>
#include <cuda_fp16.h>

// GCN: 3x GCNConv (128->64->64->2) + head (2->16), 100k nodes, 1.6M edges.
// agg[d] = dis[d] * ( sum_{e: dst=d} hs[src_e] + hs[d] ),  hs = (x@W)*dis.
// CSR gather (fp16 payload, 8 lanes x 16B per dst, index double-buffering),
// rank-based CSR fill (no atomics in fill), tf32 mma layers 0/1, layer-2
// projection fused into layer-1 gather. g_cnt is re-zeroed by k_final.

#define MAXN 100000
#define MAXE 1600000
#define NF 128
#define NH 64
#define NCLS 16
#define SCANB 1024

__device__ __align__(16) float  g_dis[MAXN];
__device__ __align__(16) __half g_hsh[MAXN * NH];   // fp16 gather payload
__device__ __align__(16) float  g_h  [MAXN * NH];   // fp32 activations / 2-wide payload
__device__ int g_cnt[MAXN];                         // zero at call entry (k_final re-zeroes)
__device__ int g_rowstart[MAXN + 1];
__device__ int g_rank[MAXE];                        // per-edge rank within dst bucket
__device__ int g_bsum[128];
__device__ int g_csr[MAXE];

// ---------------------------------------------------------------- CSR build
// histogram; atomic return value = this edge's rank within its dst bucket
__global__ void k_hist(const int* __restrict__ ei, int E) {
    int e = blockIdx.x * blockDim.x + threadIdx.x;
    if (e >= E) return;
    g_rank[e] = atomicAdd(&g_cnt[ei[E + e]], 1);
}
// per-block exclusive scan via warp shuffles
__global__ __launch_bounds__(SCANB) void k_scan1(int n) {
    __shared__ int wsum[32];
    const int tid = threadIdx.x, lane = tid & 31, warp = tid >> 5;
    const int i = blockIdx.x * SCANB + tid;
    int v = (i < n) ? g_cnt[i] : 0;
    int x = v;
#pragma unroll
    for (int off = 1; off < 32; off <<= 1) {
        int t = __shfl_up_sync(0xffffffffu, x, off);
        if (lane >= off) x += t;
    }
    if (lane == 31) wsum[warp] = x;
    __syncthreads();
    if (warp == 0) {
        int s = wsum[lane];
        int y = s;
#pragma unroll
        for (int off = 1; off < 32; off <<= 1) {
            int t = __shfl_up_sync(0xffffffffu, y, off);
            if (lane >= off) y += t;
        }
        wsum[lane] = y - s;
        if (lane == 31) g_bsum[blockIdx.x] = y;
    }
    __syncthreads();
    if (i < n) g_rowstart[i] = wsum[warp] + x - v;
}
// single-warp shuffle scan of block sums (each lane covers 4), then finalize
__global__ void k_scan_fin(int n, int nb) {
    __shared__ int sh[128];                            // inclusive prefix of bsum
    int tid = threadIdx.x;
    if (tid < 32) {
        int base = tid * 4;
        int v0 = (base + 0 < nb) ? g_bsum[base + 0] : 0;
        int v1 = (base + 1 < nb) ? g_bsum[base + 1] : 0;
        int v2 = (base + 2 < nb) ? g_bsum[base + 2] : 0;
        int v3 = (base + 3 < nb) ? g_bsum[base + 3] : 0;
        int s = v0 + v1 + v2 + v3;
        int x = s;
#pragma unroll
        for (int off = 1; off < 32; off <<= 1) {
            int t = __shfl_up_sync(0xffffffffu, x, off);
            if (tid >= off) x += t;
        }
        int excl = x - s;
        sh[base + 0] = excl + v0;
        sh[base + 1] = excl + v0 + v1;
        sh[base + 2] = excl + v0 + v1 + v2;
        sh[base + 3] = excl + s;
    }
    __syncthreads();
    int i = blockIdx.x * blockDim.x + tid;
    if (i >= n) return;
    int blk = i >> 10;
    int off = (blk > 0) ? sh[blk - 1] : 0;
    int rs = g_rowstart[i] + off;
    g_rowstart[i] = rs;
    g_dis[i] = rsqrtf((float)g_cnt[i] + 1.0f);
    if (i == n - 1) g_rowstart[n] = rs + g_cnt[i];
}
// pure-store fill using precomputed ranks (no atomics)
__global__ void k_fill(const int* __restrict__ ei, int E) {
    int e = blockIdx.x * blockDim.x + threadIdx.x;
    if (e >= E) return;
    int d = ei[E + e];
    g_csr[g_rowstart[d] + g_rank[e]] = ei[e];
}

// ---------------------------------------------------------------- tf32 helpers
__device__ __forceinline__ float to_tf32(float x) {
    float r;
    asm("cvt.rna.tf32.f32 %0, %1;" : "=f"(r) : "f"(x));
    return r;
}
__device__ __forceinline__ void mma_tf32(float c[4], unsigned a0, unsigned a1,
                                         unsigned a2, unsigned a3, unsigned b0, unsigned b1) {
    asm volatile(
        "mma.sync.aligned.m16n8k8.row.col.f32.tf32.tf32.f32 "
        "{%0,%1,%2,%3}, {%4,%5,%6,%7}, {%8,%9}, {%0,%1,%2,%3};"
        : "+f"(c[0]), "+f"(c[1]), "+f"(c[2]), "+f"(c[3])
        : "r"(a0), "r"(a1), "r"(a2), "r"(a3), "r"(b0), "r"(b1));
}

// ---------------------------------------------------------------- tf32 tensor-core GEMM (K -> 64)
template <int K, bool FROM_GLOBAL>
__global__ __launch_bounds__(128) void k_gemm_tc(const float* __restrict__ Ain,
                                                 const float* __restrict__ W, int n) {
    __shared__ float As[64][36];
    __shared__ float Ws[K][72];
    const int tid = threadIdx.x;
    const float* __restrict__ A = FROM_GLOBAL ? Ain : (const float*)g_h;
    const int row0 = blockIdx.x * 64;

    for (int i = tid; i < K * 16; i += 128) {
        int k = i >> 4, c = (i & 15) << 2;
        float4 v = *reinterpret_cast<const float4*>(&W[k * 64 + c]);
        Ws[k][c + 0] = to_tf32(v.x);
        Ws[k][c + 1] = to_tf32(v.y);
        Ws[k][c + 2] = to_tf32(v.z);
        Ws[k][c + 3] = to_tf32(v.w);
    }

    const int lane = tid & 31, warp = tid >> 5;
    const int g = lane >> 2, t = lane & 3;
    const int r0 = warp * 16;

    float c[8][4];
#pragma unroll
    for (int i = 0; i < 8; i++)
#pragma unroll
        for (int j = 0; j < 4; j++) c[i][j] = 0.0f;

    for (int kc = 0; kc < K; kc += 32) {
        __syncthreads();
#pragma unroll
        for (int j = 0; j < 4; j++) {
            int idx = tid + j * 128;
            int r = idx >> 3, c4 = (idx & 7) << 2;
            int row = row0 + r;
            float4 v = make_float4(0.f, 0.f, 0.f, 0.f);
            if (row < n) v = *reinterpret_cast<const float4*>(&A[(size_t)row * K + kc + c4]);
            As[r][c4 + 0] = to_tf32(v.x);
            As[r][c4 + 1] = to_tf32(v.y);
            As[r][c4 + 2] = to_tf32(v.z);
            As[r][c4 + 3] = to_tf32(v.w);
        }
        __syncthreads();
#pragma unroll
        for (int ks = 0; ks < 32; ks += 8) {
            unsigned a0 = __float_as_uint(As[r0 + g    ][ks + t    ]);
            unsigned a1 = __float_as_uint(As[r0 + g + 8][ks + t    ]);
            unsigned a2 = __float_as_uint(As[r0 + g    ][ks + t + 4]);
            unsigned a3 = __float_as_uint(As[r0 + g + 8][ks + t + 4]);
#pragma unroll
            for (int nt = 0; nt < 8; nt++) {
                unsigned b0 = __float_as_uint(Ws[kc + ks + t    ][nt * 8 + g]);
                unsigned b1 = __float_as_uint(Ws[kc + ks + t + 4][nt * 8 + g]);
                mma_tf32(c[nt], a0, a1, a2, a3, b0, b1);
            }
        }
    }

    int rowA = row0 + r0 + g;
    int rowB = rowA + 8;
    float sA = (rowA < n) ? g_dis[rowA] : 0.0f;
    float sB = (rowB < n) ? g_dis[rowB] : 0.0f;
#pragma unroll
    for (int nt = 0; nt < 8; nt++) {
        int col = nt * 8 + 2 * t;
        if (rowA < n)
            *reinterpret_cast<__half2*>(&g_hsh[rowA * NH + col]) =
                __floats2half2_rn(c[nt][0] * sA, c[nt][1] * sA);
        if (rowB < n)
            *reinterpret_cast<__half2*>(&g_hsh[rowB * NH + col]) =
                __floats2half2_rn(c[nt][2] * sB, c[nt][3] * sB);
    }
}

// ---------------------------------------------------------------- fp16 gather, 8 lanes x 16B per dst
// Index double-buffering: prefetch next CSR quad while current payloads are in flight.
struct F8 { float4 a, b; };
__device__ __forceinline__ void acc8(F8& A, uint4 u) {
    float2 p0 = __half22float2(*reinterpret_cast<__half2*>(&u.x));
    float2 p1 = __half22float2(*reinterpret_cast<__half2*>(&u.y));
    float2 p2 = __half22float2(*reinterpret_cast<__half2*>(&u.z));
    float2 p3 = __half22float2(*reinterpret_cast<__half2*>(&u.w));
    A.a.x += p0.x; A.a.y += p0.y; A.a.z += p1.x; A.a.w += p1.y;
    A.b.x += p2.x; A.b.y += p2.y; A.b.z += p3.x; A.b.w += p3.y;
}
__device__ __forceinline__ F8 gather_row8(int d, int f8) {
    int j   = g_rowstart[d];
    int end = g_rowstart[d + 1];
    F8 A = {make_float4(0.f, 0.f, 0.f, 0.f), make_float4(0.f, 0.f, 0.f, 0.f)};
    F8 B = {make_float4(0.f, 0.f, 0.f, 0.f), make_float4(0.f, 0.f, 0.f, 0.f)};
    acc8(A, *reinterpret_cast<const uint4*>(&g_hsh[d * NH + f8]));   // self-loop
    if (j + 3 < end) {
        int s0 = __ldg(&g_csr[j]);
        int s1 = __ldg(&g_csr[j + 1]);
        int s2 = __ldg(&g_csr[j + 2]);
        int s3 = __ldg(&g_csr[j + 3]);
        j += 4;
        while (j + 3 < end) {
            int t0 = __ldg(&g_csr[j]);
            int t1 = __ldg(&g_csr[j + 1]);
            int t2 = __ldg(&g_csr[j + 2]);
            int t3 = __ldg(&g_csr[j + 3]);
            uint4 u0 = *reinterpret_cast<const uint4*>(&g_hsh[s0 * NH + f8]);
            uint4 u1 = *reinterpret_cast<const uint4*>(&g_hsh[s1 * NH + f8]);
            uint4 u2 = *reinterpret_cast<const uint4*>(&g_hsh[s2 * NH + f8]);
            uint4 u3 = *reinterpret_cast<const uint4*>(&g_hsh[s3 * NH + f8]);
            acc8(A, u0); acc8(B, u1); acc8(A, u2); acc8(B, u3);
            s0 = t0; s1 = t1; s2 = t2; s3 = t3;
            j += 4;
        }
        uint4 u0 = *reinterpret_cast<const uint4*>(&g_hsh[s0 * NH + f8]);
        uint4 u1 = *reinterpret_cast<const uint4*>(&g_hsh[s1 * NH + f8]);
        uint4 u2 = *reinterpret_cast<const uint4*>(&g_hsh[s2 * NH + f8]);
        uint4 u3 = *reinterpret_cast<const uint4*>(&g_hsh[s3 * NH + f8]);
        acc8(A, u0); acc8(B, u1); acc8(A, u2); acc8(B, u3);
    }
    for (; j < end; j++) {
        int s = __ldg(&g_csr[j]);
        acc8(A, *reinterpret_cast<const uint4*>(&g_hsh[s * NH + f8]));
    }
    A.a.x += B.a.x; A.a.y += B.a.y; A.a.z += B.a.z; A.a.w += B.a.w;
    A.b.x += B.b.x; A.b.y += B.b.y; A.b.z += B.b.z; A.b.w += B.b.w;
    return A;
}

// ---------------------------------------------------------------- layer-0 gather: h = dis*agg + b
__global__ void k_gather_l0(const float* __restrict__ b, int n) {
    int idx = blockIdx.x * blockDim.x + threadIdx.x;
    int d = idx >> 3;
    if (d >= n) return;
    int f8 = (idx & 7) << 3;
    F8 A = gather_row8(d, f8);
    float sc = g_dis[d];
    float4 b0 = *reinterpret_cast<const float4*>(&b[f8]);
    float4 b1 = *reinterpret_cast<const float4*>(&b[f8 + 4]);
    *reinterpret_cast<float4*>(&g_h[d * NH + f8]) =
        make_float4(sc * A.a.x + b0.x, sc * A.a.y + b0.y, sc * A.a.z + b0.z, sc * A.a.w + b0.w);
    *reinterpret_cast<float4*>(&g_h[d * NH + f8 + 4]) =
        make_float4(sc * A.b.x + b1.x, sc * A.b.y + b1.y, sc * A.b.z + b1.z, sc * A.b.w + b1.w);
}

// ---------------------------------------------------------------- layer-1 gather fused with 64->2 proj
__device__ __forceinline__ float2 tanh_h2(float a, float b) {
    __half2 p = __floats2half2_rn(a, b);
    asm("tanh.approx.f16x2 %0, %0;" : "+r"(*reinterpret_cast<unsigned*>(&p)));
    return __half22float2(p);
}
__global__ void k_gather_l1(const float* __restrict__ b1, const float* __restrict__ W2, int n) {
    __shared__ float sW2[NH * 2];
    int tid = threadIdx.x;
    if (tid < NH * 2) sW2[tid] = W2[tid];
    __syncthreads();
    int idx = blockIdx.x * blockDim.x + tid;
    int d = idx >> 3;
    bool active = (d < n);
    int dc = active ? d : (n - 1);
    int f8 = (idx & 7) << 3;
    F8 A = gather_row8(dc, f8);
    float sc = g_dis[dc];
    float4 bb0 = *reinterpret_cast<const float4*>(&b1[f8]);
    float4 bb1 = *reinterpret_cast<const float4*>(&b1[f8 + 4]);
    float2 t0 = tanh_h2(sc * A.a.x + bb0.x, sc * A.a.y + bb0.y);
    float2 t1 = tanh_h2(sc * A.a.z + bb0.z, sc * A.a.w + bb0.w);
    float2 t2 = tanh_h2(sc * A.b.x + bb1.x, sc * A.b.y + bb1.y);
    float2 t3 = tanh_h2(sc * A.b.z + bb1.z, sc * A.b.w + bb1.w);
    float h[8] = {t0.x, t0.y, t1.x, t1.y, t2.x, t2.y, t3.x, t3.y};
    float a0 = 0.f, a1 = 0.f;
#pragma unroll
    for (int k = 0; k < 8; k++) {
        a0 += h[k] * sW2[2 * (f8 + k)];
        a1 += h[k] * sW2[2 * (f8 + k) + 1];
    }
#pragma unroll
    for (int off = 4; off; off >>= 1) {
        a0 += __shfl_xor_sync(0xffffffffu, a0, off);
        a1 += __shfl_xor_sync(0xffffffffu, a1, off);
    }
    if (active && (idx & 7) == 0)
        *reinterpret_cast<float2*>(&g_h[2 * d]) = make_float2(a0 * sc, a1 * sc);
}

// ---------------------------------------------------------------- final: gather(2, fp32) + tanh + head
// Also zeroes g_cnt for the next kernel_launch call.
__global__ void k_final(const float* __restrict__ b2, const float* __restrict__ Wc,
                        const float* __restrict__ bc, float* __restrict__ out, int n) {
    __shared__ float sWc[2 * NCLS];
    __shared__ float sbc[NCLS];
    __shared__ float sb2[2];
    int tid = threadIdx.x;
    if (tid < 2 * NCLS) sWc[tid] = Wc[tid];
    if (tid < NCLS) sbc[tid] = bc[tid];
    if (tid < 2) sb2[tid] = b2[tid];
    __syncthreads();
    int d = blockIdx.x * blockDim.x + tid;
    if (d >= n) return;
    int start = g_rowstart[d];
    int end   = g_rowstart[d + 1];
    g_cnt[d] = 0;                                     // reset for next call
    float2 acc = *reinterpret_cast<const float2*>(&g_h[2 * d]);   // self-loop
    float2 a1 = make_float2(0.f, 0.f);
    int j = start;
    for (; j + 1 < end; j += 2) {
        int s0 = __ldg(&g_csr[j]);
        int s1 = __ldg(&g_csr[j + 1]);
        float2 v0 = *reinterpret_cast<const float2*>(&g_h[2 * s0]);
        float2 v1 = *reinterpret_cast<const float2*>(&g_h[2 * s1]);
        acc.x += v0.x; acc.y += v0.y;
        a1.x  += v1.x; a1.y  += v1.y;
    }
    if (j < end) {
        float2 v = *reinterpret_cast<const float2*>(&g_h[2 * __ldg(&g_csr[j])]);
        acc.x += v.x; acc.y += v.y;
    }
    acc.x += a1.x; acc.y += a1.y;
    float sc = g_dis[d];
    float e0 = tanhf(sc * acc.x + sb2[0]);
    float e1 = tanhf(sc * acc.y + sb2[1]);
    float o[NCLS];
#pragma unroll
    for (int j2 = 0; j2 < NCLS; j2++) o[j2] = e0 * sWc[j2] + e1 * sWc[NCLS + j2] + sbc[j2];
    float4* ov = reinterpret_cast<float4*>(out + (size_t)d * NCLS);
#pragma unroll
    for (int j2 = 0; j2 < NCLS / 4; j2++)
        ov[j2] = make_float4(o[4 * j2], o[4 * j2 + 1], o[4 * j2 + 2], o[4 * j2 + 3]);
    *reinterpret_cast<float2*>(out + (size_t)n * NCLS + 2LL * d) = make_float2(e0, e1);
}

extern "C" void kernel_launch(void* const* d_in, const int* in_sizes, int n_in,
                              void* d_out, int out_size) {
    const float* x  = (const float*)d_in[0];
    const int*   ei = (const int*)d_in[1];            // int32 (JAX demotes int64)
    const float* W0 = (const float*)d_in[2];
    const float* b0 = (const float*)d_in[3];
    const float* W1 = (const float*)d_in[4];
    const float* b1 = (const float*)d_in[5];
    const float* W2 = (const float*)d_in[6];
    const float* b2 = (const float*)d_in[7];
    const float* Wc = (const float*)d_in[8];
    const float* bc = (const float*)d_in[9];
    float* out = (float*)d_out;

    const int n = in_sizes[0] / NF;        // 100000
    const int E = in_sizes[1] / 2;         // 1600000

    const int B = 256;
    const int nb = (n + SCANB - 1) / SCANB;
    const int gemmBlocks = (n + 63) / 64;
    const int gatherBlocks = (n * 8 + B - 1) / B;

    // CSR build + dis (g_cnt zeroed by previous call's k_final / initial image)
    k_hist<<<(E + B - 1) / B, B>>>(ei, E);             // launch 1
    k_scan1<<<nb, SCANB>>>(n);                         // launch 2
    k_scan_fin<<<(n + B - 1) / B, B>>>(n, nb);         // launch 3
    k_fill<<<(E + B - 1) / B, B>>>(ei, E);             // launch 4 (ncu profiles this)

    // ---- layer 0: 128 -> 64, no activation
    k_gemm_tc<NF, true><<<gemmBlocks, 128>>>(x, W0, n);
    k_gather_l0<<<gatherBlocks, B>>>(b0, n);

    // ---- layer 1: 64 -> 64 (tanh) fused with layer-2 64->2 projection
    k_gemm_tc<NH, false><<<gemmBlocks, 128>>>(nullptr, W1, n);
    k_gather_l1<<<gatherBlocks, B>>>(b1, W2, n);

    // ---- layer 2 gather + tanh + head 2 -> 16
    k_final<<<(n + B - 1) / B, B>>>(b2, Wc, bc, out, n);
}

// round 16
// speedup vs baseline: 1.3448x; 1.3448x over previous
#include <cuda_runtime.h>
#include <cuda_fp16.h>

// GCN: 3x GCNConv (128->64->64->2) + head (2->16), 100k nodes, 1.6M edges.
// agg[d] = dis[d] * ( sum_{e: dst=d} hs[src_e] + hs[d] ),  hs = (x@W)*dis.
// CSR gather (fp16 payload, 8 lanes x 16B per dst, plain unroll-4 loop --
// do NOT software-pipeline it, that breaks ptxas load batching: R13 +62us),
// rank-based CSR fill, tf32 mma layers 0/1, layer-2 projection fused into
// layer-1 gather. g_cnt is re-zeroed by k_final for the next call.

#define MAXN 100000
#define MAXE 1600000
#define NF 128
#define NH 64
#define NCLS 16
#define SCANB 1024

__device__ __align__(16) float  g_dis[MAXN];
__device__ __align__(16) __half g_hsh[MAXN * NH];   // fp16 gather payload
__device__ __align__(16) float  g_h  [MAXN * NH];   // fp32 activations / 2-wide payload
__device__ int g_cnt[MAXN];                         // zero at call entry (k_final re-zeroes)
__device__ int g_rowstart[MAXN + 1];
__device__ int g_rank[MAXE];                        // per-edge rank within dst bucket
__device__ int g_bsum[128];
__device__ int g_csr[MAXE];

// ---------------------------------------------------------------- CSR build
// histogram; atomic return value = this edge's rank within its dst bucket
__global__ void k_hist(const int* __restrict__ ei, int E) {
    int e = blockIdx.x * blockDim.x + threadIdx.x;
    if (e >= E) return;
    g_rank[e] = atomicAdd(&g_cnt[ei[E + e]], 1);
}
// per-block exclusive scan via warp shuffles
__global__ __launch_bounds__(SCANB) void k_scan1(int n) {
    __shared__ int wsum[32];
    const int tid = threadIdx.x, lane = tid & 31, warp = tid >> 5;
    const int i = blockIdx.x * SCANB + tid;
    int v = (i < n) ? g_cnt[i] : 0;
    int x = v;
#pragma unroll
    for (int off = 1; off < 32; off <<= 1) {
        int t = __shfl_up_sync(0xffffffffu, x, off);
        if (lane >= off) x += t;
    }
    if (lane == 31) wsum[warp] = x;
    __syncthreads();
    if (warp == 0) {
        int s = wsum[lane];
        int y = s;
#pragma unroll
        for (int off = 1; off < 32; off <<= 1) {
            int t = __shfl_up_sync(0xffffffffu, y, off);
            if (lane >= off) y += t;
        }
        wsum[lane] = y - s;
        if (lane == 31) g_bsum[blockIdx.x] = y;
    }
    __syncthreads();
    if (i < n) g_rowstart[i] = wsum[warp] + x - v;
}
// single-warp shuffle scan of block sums (each lane covers 4), then finalize
__global__ void k_scan_fin(int n, int nb) {
    __shared__ int sh[128];                            // inclusive prefix of bsum
    int tid = threadIdx.x;
    if (tid < 32) {
        int base = tid * 4;
        int v0 = (base + 0 < nb) ? g_bsum[base + 0] : 0;
        int v1 = (base + 1 < nb) ? g_bsum[base + 1] : 0;
        int v2 = (base + 2 < nb) ? g_bsum[base + 2] : 0;
        int v3 = (base + 3 < nb) ? g_bsum[base + 3] : 0;
        int s = v0 + v1 + v2 + v3;
        int x = s;
#pragma unroll
        for (int off = 1; off < 32; off <<= 1) {
            int t = __shfl_up_sync(0xffffffffu, x, off);
            if (tid >= off) x += t;
        }
        int excl = x - s;
        sh[base + 0] = excl + v0;
        sh[base + 1] = excl + v0 + v1;
        sh[base + 2] = excl + v0 + v1 + v2;
        sh[base + 3] = excl + s;
    }
    __syncthreads();
    int i = blockIdx.x * blockDim.x + tid;
    if (i >= n) return;
    int blk = i >> 10;
    int off = (blk > 0) ? sh[blk - 1] : 0;
    int rs = g_rowstart[i] + off;
    g_rowstart[i] = rs;
    g_dis[i] = rsqrtf((float)g_cnt[i] + 1.0f);
    if (i == n - 1) g_rowstart[n] = rs + g_cnt[i];
}
// pure-store fill using precomputed ranks (no atomics)
__global__ void k_fill(const int* __restrict__ ei, int E) {
    int e = blockIdx.x * blockDim.x + threadIdx.x;
    if (e >= E) return;
    int d = ei[E + e];
    g_csr[g_rowstart[d] + g_rank[e]] = ei[e];
}

// ---------------------------------------------------------------- tf32 helpers
__device__ __forceinline__ float to_tf32(float x) {
    float r;
    asm("cvt.rna.tf32.f32 %0, %1;" : "=f"(r) : "f"(x));
    return r;
}
__device__ __forceinline__ void mma_tf32(float c[4], unsigned a0, unsigned a1,
                                         unsigned a2, unsigned a3, unsigned b0, unsigned b1) {
    asm volatile(
        "mma.sync.aligned.m16n8k8.row.col.f32.tf32.tf32.f32 "
        "{%0,%1,%2,%3}, {%4,%5,%6,%7}, {%8,%9}, {%0,%1,%2,%3};"
        : "+f"(c[0]), "+f"(c[1]), "+f"(c[2]), "+f"(c[3])
        : "r"(a0), "r"(a1), "r"(a2), "r"(a3), "r"(b0), "r"(b1));
}

// ---------------------------------------------------------------- tf32 tensor-core GEMM (K -> 64)
template <int K, bool FROM_GLOBAL>
__global__ __launch_bounds__(128) void k_gemm_tc(const float* __restrict__ Ain,
                                                 const float* __restrict__ W, int n) {
    __shared__ float As[64][36];
    __shared__ float Ws[K][72];
    const int tid = threadIdx.x;
    const float* __restrict__ A = FROM_GLOBAL ? Ain : (const float*)g_h;
    const int row0 = blockIdx.x * 64;

    for (int i = tid; i < K * 16; i += 128) {
        int k = i >> 4, c = (i & 15) << 2;
        float4 v = *reinterpret_cast<const float4*>(&W[k * 64 + c]);
        Ws[k][c + 0] = to_tf32(v.x);
        Ws[k][c + 1] = to_tf32(v.y);
        Ws[k][c + 2] = to_tf32(v.z);
        Ws[k][c + 3] = to_tf32(v.w);
    }

    const int lane = tid & 31, warp = tid >> 5;
    const int g = lane >> 2, t = lane & 3;
    const int r0 = warp * 16;

    float c[8][4];
#pragma unroll
    for (int i = 0; i < 8; i++)
#pragma unroll
        for (int j = 0; j < 4; j++) c[i][j] = 0.0f;

    for (int kc = 0; kc < K; kc += 32) {
        __syncthreads();
#pragma unroll
        for (int j = 0; j < 4; j++) {
            int idx = tid + j * 128;
            int r = idx >> 3, c4 = (idx & 7) << 2;
            int row = row0 + r;
            float4 v = make_float4(0.f, 0.f, 0.f, 0.f);
            if (row < n) v = *reinterpret_cast<const float4*>(&A[(size_t)row * K + kc + c4]);
            As[r][c4 + 0] = to_tf32(v.x);
            As[r][c4 + 1] = to_tf32(v.y);
            As[r][c4 + 2] = to_tf32(v.z);
            As[r][c4 + 3] = to_tf32(v.w);
        }
        __syncthreads();
#pragma unroll
        for (int ks = 0; ks < 32; ks += 8) {
            unsigned a0 = __float_as_uint(As[r0 + g    ][ks + t    ]);
            unsigned a1 = __float_as_uint(As[r0 + g + 8][ks + t    ]);
            unsigned a2 = __float_as_uint(As[r0 + g    ][ks + t + 4]);
            unsigned a3 = __float_as_uint(As[r0 + g + 8][ks + t + 4]);
#pragma unroll
            for (int nt = 0; nt < 8; nt++) {
                unsigned b0 = __float_as_uint(Ws[kc + ks + t    ][nt * 8 + g]);
                unsigned b1 = __float_as_uint(Ws[kc + ks + t + 4][nt * 8 + g]);
                mma_tf32(c[nt], a0, a1, a2, a3, b0, b1);
            }
        }
    }

    int rowA = row0 + r0 + g;
    int rowB = rowA + 8;
    float sA = (rowA < n) ? g_dis[rowA] : 0.0f;
    float sB = (rowB < n) ? g_dis[rowB] : 0.0f;
#pragma unroll
    for (int nt = 0; nt < 8; nt++) {
        int col = nt * 8 + 2 * t;
        if (rowA < n)
            *reinterpret_cast<__half2*>(&g_hsh[rowA * NH + col]) =
                __floats2half2_rn(c[nt][0] * sA, c[nt][1] * sA);
        if (rowB < n)
            *reinterpret_cast<__half2*>(&g_hsh[rowB * NH + col]) =
                __floats2half2_rn(c[nt][2] * sB, c[nt][3] * sB);
    }
}

// ---------------------------------------------------------------- fp16 gather, 8 lanes x 16B per dst
// Plain unroll-4 body (R12 form). Keep the 4 index loads + 4 payload loads
// adjacent in one iteration so ptxas front-batches the LDG.128s.
struct F8 { float4 a, b; };
__device__ __forceinline__ void acc8(F8& A, uint4 u) {
    float2 p0 = __half22float2(*reinterpret_cast<__half2*>(&u.x));
    float2 p1 = __half22float2(*reinterpret_cast<__half2*>(&u.y));
    float2 p2 = __half22float2(*reinterpret_cast<__half2*>(&u.z));
    float2 p3 = __half22float2(*reinterpret_cast<__half2*>(&u.w));
    A.a.x += p0.x; A.a.y += p0.y; A.a.z += p1.x; A.a.w += p1.y;
    A.b.x += p2.x; A.b.y += p2.y; A.b.z += p3.x; A.b.w += p3.y;
}
__device__ __forceinline__ F8 gather_row8(int d, int f8) {
    int start = g_rowstart[d];
    int end   = g_rowstart[d + 1];
    F8 A = {make_float4(0.f, 0.f, 0.f, 0.f), make_float4(0.f, 0.f, 0.f, 0.f)};
    F8 B = {make_float4(0.f, 0.f, 0.f, 0.f), make_float4(0.f, 0.f, 0.f, 0.f)};
    acc8(A, *reinterpret_cast<const uint4*>(&g_hsh[d * NH + f8]));   // self-loop
    int j = start;
    for (; j + 3 < end; j += 4) {
        int s0 = __ldg(&g_csr[j]);
        int s1 = __ldg(&g_csr[j + 1]);
        int s2 = __ldg(&g_csr[j + 2]);
        int s3 = __ldg(&g_csr[j + 3]);
        uint4 u0 = *reinterpret_cast<const uint4*>(&g_hsh[s0 * NH + f8]);
        uint4 u1 = *reinterpret_cast<const uint4*>(&g_hsh[s1 * NH + f8]);
        uint4 u2 = *reinterpret_cast<const uint4*>(&g_hsh[s2 * NH + f8]);
        uint4 u3 = *reinterpret_cast<const uint4*>(&g_hsh[s3 * NH + f8]);
        acc8(A, u0); acc8(B, u1); acc8(A, u2); acc8(B, u3);
    }
    for (; j < end; j++) {
        int s = __ldg(&g_csr[j]);
        acc8(A, *reinterpret_cast<const uint4*>(&g_hsh[s * NH + f8]));
    }
    A.a.x += B.a.x; A.a.y += B.a.y; A.a.z += B.a.z; A.a.w += B.a.w;
    A.b.x += B.b.x; A.b.y += B.b.y; A.b.z += B.b.z; A.b.w += B.b.w;
    return A;
}

// ---------------------------------------------------------------- layer-0 gather: h = dis*agg + b
__global__ void k_gather_l0(const float* __restrict__ b, int n) {
    int idx = blockIdx.x * blockDim.x + threadIdx.x;
    int d = idx >> 3;
    if (d >= n) return;
    int f8 = (idx & 7) << 3;
    F8 A = gather_row8(d, f8);
    float sc = g_dis[d];
    float4 b0 = *reinterpret_cast<const float4*>(&b[f8]);
    float4 b1 = *reinterpret_cast<const float4*>(&b[f8 + 4]);
    *reinterpret_cast<float4*>(&g_h[d * NH + f8]) =
        make_float4(sc * A.a.x + b0.x, sc * A.a.y + b0.y, sc * A.a.z + b0.z, sc * A.a.w + b0.w);
    *reinterpret_cast<float4*>(&g_h[d * NH + f8 + 4]) =
        make_float4(sc * A.b.x + b1.x, sc * A.b.y + b1.y, sc * A.b.z + b1.z, sc * A.b.w + b1.w);
}

// ---------------------------------------------------------------- layer-1 gather fused with 64->2 proj
__device__ __forceinline__ float2 tanh_h2(float a, float b) {
    __half2 p = __floats2half2_rn(a, b);
    asm("tanh.approx.f16x2 %0, %0;" : "+r"(*reinterpret_cast<unsigned*>(&p)));
    return __half22float2(p);
}
__global__ void k_gather_l1(const float* __restrict__ b1, const float* __restrict__ W2, int n) {
    __shared__ float sW2[NH * 2];
    int tid = threadIdx.x;
    if (tid < NH * 2) sW2[tid] = W2[tid];
    __syncthreads();
    int idx = blockIdx.x * blockDim.x + tid;
    int d = idx >> 3;
    bool active = (d < n);
    int dc = active ? d : (n - 1);
    int f8 = (idx & 7) << 3;
    F8 A = gather_row8(dc, f8);
    float sc = g_dis[dc];
    float4 bb0 = *reinterpret_cast<const float4*>(&b1[f8]);
    float4 bb1 = *reinterpret_cast<const float4*>(&b1[f8 + 4]);
    float2 t0 = tanh_h2(sc * A.a.x + bb0.x, sc * A.a.y + bb0.y);
    float2 t1 = tanh_h2(sc * A.a.z + bb0.z, sc * A.a.w + bb0.w);
    float2 t2 = tanh_h2(sc * A.b.x + bb1.x, sc * A.b.y + bb1.y);
    float2 t3 = tanh_h2(sc * A.b.z + bb1.z, sc * A.b.w + bb1.w);
    float h[8] = {t0.x, t0.y, t1.x, t1.y, t2.x, t2.y, t3.x, t3.y};
    float a0 = 0.f, a1 = 0.f;
#pragma unroll
    for (int k = 0; k < 8; k++) {
        a0 += h[k] * sW2[2 * (f8 + k)];
        a1 += h[k] * sW2[2 * (f8 + k) + 1];
    }
#pragma unroll
    for (int off = 4; off; off >>= 1) {
        a0 += __shfl_xor_sync(0xffffffffu, a0, off);
        a1 += __shfl_xor_sync(0xffffffffu, a1, off);
    }
    if (active && (idx & 7) == 0)
        *reinterpret_cast<float2*>(&g_h[2 * d]) = make_float2(a0 * sc, a1 * sc);
}

// ---------------------------------------------------------------- final: gather(2, fp32) + tanh + head
// Also zeroes g_cnt for the next kernel_launch call.
__global__ void k_final(const float* __restrict__ b2, const float* __restrict__ Wc,
                        const float* __restrict__ bc, float* __restrict__ out, int n) {
    __shared__ float sWc[2 * NCLS];
    __shared__ float sbc[NCLS];
    __shared__ float sb2[2];
    int tid = threadIdx.x;
    if (tid < 2 * NCLS) sWc[tid] = Wc[tid];
    if (tid < NCLS) sbc[tid] = bc[tid];
    if (tid < 2) sb2[tid] = b2[tid];
    __syncthreads();
    int d = blockIdx.x * blockDim.x + tid;
    if (d >= n) return;
    int start = g_rowstart[d];
    int end   = g_rowstart[d + 1];
    g_cnt[d] = 0;                                     // reset for next call
    float2 acc = *reinterpret_cast<const float2*>(&g_h[2 * d]);   // self-loop
    float2 a1 = make_float2(0.f, 0.f);
    int j = start;
    for (; j + 1 < end; j += 2) {
        int s0 = __ldg(&g_csr[j]);
        int s1 = __ldg(&g_csr[j + 1]);
        float2 v0 = *reinterpret_cast<const float2*>(&g_h[2 * s0]);
        float2 v1 = *reinterpret_cast<const float2*>(&g_h[2 * s1]);
        acc.x += v0.x; acc.y += v0.y;
        a1.x  += v1.x; a1.y  += v1.y;
    }
    if (j < end) {
        float2 v = *reinterpret_cast<const float2*>(&g_h[2 * __ldg(&g_csr[j])]);
        acc.x += v.x; acc.y += v.y;
    }
    acc.x += a1.x; acc.y += a1.y;
    float sc = g_dis[d];
    float e0 = tanhf(sc * acc.x + sb2[0]);
    float e1 = tanhf(sc * acc.y + sb2[1]);
    float o[NCLS];
#pragma unroll
    for (int j2 = 0; j2 < NCLS; j2++) o[j2] = e0 * sWc[j2] + e1 * sWc[NCLS + j2] + sbc[j2];
    float4* ov = reinterpret_cast<float4*>(out + (size_t)d * NCLS);
#pragma unroll
    for (int j2 = 0; j2 < NCLS / 4; j2++)
        ov[j2] = make_float4(o[4 * j2], o[4 * j2 + 1], o[4 * j2 + 2], o[4 * j2 + 3]);
    *reinterpret_cast<float2*>(out + (size_t)n * NCLS + 2LL * d) = make_float2(e0, e1);
}

extern "C" void kernel_launch(void* const* d_in, const int* in_sizes, int n_in,
                              void* d_out, int out_size) {
    const float* x  = (const float*)d_in[0];
    const int*   ei = (const int*)d_in[1];            // int32 (JAX demotes int64)
    const float* W0 = (const float*)d_in[2];
    const float* b0 = (const float*)d_in[3];
    const float* W1 = (const float*)d_in[4];
    const float* b1 = (const float*)d_in[5];
    const float* W2 = (const float*)d_in[6];
    const float* b2 = (const float*)d_in[7];
    const float* Wc = (const float*)d_in[8];
    const float* bc = (const float*)d_in[9];
    float* out = (float*)d_out;

    const int n = in_sizes[0] / NF;        // 100000
    const int E = in_sizes[1] / 2;         // 1600000

    const int B = 256;
    const int nb = (n + SCANB - 1) / SCANB;
    const int gemmBlocks = (n + 63) / 64;
    const int gatherBlocks = (n * 8 + B - 1) / B;

    // CSR build + dis (g_cnt zeroed by previous call's k_final / initial image)
    k_hist<<<(E + B - 1) / B, B>>>(ei, E);
    k_scan1<<<nb, SCANB>>>(n);
    k_scan_fin<<<(n + B - 1) / B, B>>>(n, nb);
    k_fill<<<(E + B - 1) / B, B>>>(ei, E);

    // ---- layer 0: 128 -> 64, no activation
    k_gemm_tc<NF, true><<<gemmBlocks, 128>>>(x, W0, n);
    k_gather_l0<<<gatherBlocks, B>>>(b0, n);

    // ---- layer 1: 64 -> 64 (tanh) fused with layer-2 64->2 projection
    k_gemm_tc<NH, false><<<gemmBlocks, 128>>>(nullptr, W1, n);
    k_gather_l1<<<gatherBlocks, B>>>(b1, W2, n);

    // ---- layer 2 gather + tanh + head 2 -> 16
    k_final<<<(n + B - 1) / B, B>>>(b2, Wc, bc, out, n);
}